// round 1
// baseline (speedup 1.0000x reference)
#include <cuda_runtime.h>

#define D 128
#define MAX_N 100000
#define TILE_M 64
#define WPAD 132   // padded W row (floats): multiple of 4 (16B-aligned float4 rows), odd/32 -> conflict-light

// Scratch (no allocations allowed in kernel_launch; device globals are the sanctioned path)
__device__ float g_neigh[(size_t)MAX_N * D];
__device__ float g_total[D];

// ---------------------------------------------------------------------------
// Zero the accumulation buffers
// ---------------------------------------------------------------------------
__global__ void k_zero(int n4) {
    int i = blockIdx.x * blockDim.x + threadIdx.x;
    int stride = gridDim.x * blockDim.x;
    float4 z = make_float4(0.f, 0.f, 0.f, 0.f);
    float4* p = reinterpret_cast<float4*>(g_neigh);
    for (int j = i; j < n4; j += stride) p[j] = z;
    if (i < D) g_total[i] = 0.f;
}

// ---------------------------------------------------------------------------
// Column sums of features: total[c] = sum_r features[r][c]
// block = 128 threads (one per column), grid-stride over rows
// ---------------------------------------------------------------------------
__global__ void k_total(const float* __restrict__ feat, int N) {
    int c = threadIdx.x;
    float s = 0.f;
    for (int r = blockIdx.x; r < N; r += gridDim.x)
        s += feat[(size_t)r * D + c];
    atomicAdd(&g_total[c], s);
}

// ---------------------------------------------------------------------------
// Scatter: neigh_sum[dst[e]] += features[src[e]]
// One warp per edge: lane handles 4 floats (float4), vector red.add to L2.
// ---------------------------------------------------------------------------
__global__ void k_scatter(const float* __restrict__ feat,
                          const int* __restrict__ src,
                          const int* __restrict__ dst, int E) {
    int gid = blockIdx.x * blockDim.x + threadIdx.x;
    int e = gid >> 5;
    if (e >= E) return;
    int lane = gid & 31;
    int s = __ldg(src + e);
    int d = __ldg(dst + e);
    float4 v = __ldg(reinterpret_cast<const float4*>(feat + (size_t)s * D) + lane);
    float* p = g_neigh + (size_t)d * D + (lane << 2);
    asm volatile("red.global.add.v4.f32 [%0], {%1,%2,%3,%4};"
                 :: "l"(p), "f"(v.x), "f"(v.y), "f"(v.z), "f"(v.w)
                 : "memory");
}

// ---------------------------------------------------------------------------
// Fused epilogue: h = total - neigh_sum; L2-normalize rows; out = h @ W^T + b
// Block = 256 threads, TILE_M=64 rows per block.
// Phase 1: 8 warps normalize 8 rows each into smem.
// Phase 2: W^T staged in padded smem; 4x8 register micro-tile GEMM.
// ---------------------------------------------------------------------------
__global__ void k_out(const float* __restrict__ W, const float* __restrict__ b,
                      float* __restrict__ out, int N) {
    extern __shared__ float sh[];
    float* shW = sh;                 // [D][WPAD] : W transposed -> shW[k*WPAD + c] = W[c][k]
    float* shH = sh + D * WPAD;      // [TILE_M][D] normalized rows

    int tid = threadIdx.x;

    // Stage W transposed (coalesced global read, once per block)
    for (int idx = tid; idx < D * D; idx += 256) {
        int k = idx & (D - 1);
        int c = idx >> 7;
        shW[k * WPAD + c] = W[c * D + k];
    }

    int row0 = blockIdx.x * TILE_M;
    int lane = tid & 31;
    int w    = tid >> 5;

    float4 tv = reinterpret_cast<const float4*>(g_total)[lane];
    for (int r = w; r < TILE_M; r += 8) {
        int row = row0 + r;
        float4 hv = make_float4(0.f, 0.f, 0.f, 0.f);
        if (row < N) {
            float4 nv = reinterpret_cast<const float4*>(g_neigh + (size_t)row * D)[lane];
            hv.x = tv.x - nv.x;
            hv.y = tv.y - nv.y;
            hv.z = tv.z - nv.z;
            hv.w = tv.w - nv.w;
            float ss = hv.x * hv.x + hv.y * hv.y + hv.z * hv.z + hv.w * hv.w;
            #pragma unroll
            for (int o = 16; o; o >>= 1) ss += __shfl_xor_sync(0xffffffffu, ss, o);
            float inv = 1.f / fmaxf(sqrtf(ss), 1e-12f);
            hv.x *= inv; hv.y *= inv; hv.z *= inv; hv.w *= inv;
        }
        reinterpret_cast<float4*>(shH + r * D)[lane] = hv;
    }
    __syncthreads();

    // GEMM: thread (tr, tc) computes rows tr*4..+3, cols tc*8..+7
    int tr = tid >> 4;       // 0..15
    int tc = tid & 15;       // 0..15
    int c0 = tc << 3;

    float acc[4][8];
    #pragma unroll
    for (int i = 0; i < 4; i++)
        #pragma unroll
        for (int j = 0; j < 8; j++) acc[i][j] = 0.f;

    const float* hp = shH + (tr << 2) * D;

    #pragma unroll 4
    for (int k = 0; k < D; k++) {
        float4 w0 = *reinterpret_cast<const float4*>(shW + k * WPAD + c0);
        float4 w1 = *reinterpret_cast<const float4*>(shW + k * WPAD + c0 + 4);
        float wv[8] = {w0.x, w0.y, w0.z, w0.w, w1.x, w1.y, w1.z, w1.w};
        float hv[4];
        #pragma unroll
        for (int i = 0; i < 4; i++) hv[i] = hp[i * D + k];
        #pragma unroll
        for (int i = 0; i < 4; i++)
            #pragma unroll
            for (int j = 0; j < 8; j++)
                acc[i][j] = fmaf(hv[i], wv[j], acc[i][j]);
    }

    float4 b0 = *reinterpret_cast<const float4*>(b + c0);
    float4 b1 = *reinterpret_cast<const float4*>(b + c0 + 4);
    float bv[8] = {b0.x, b0.y, b0.z, b0.w, b1.x, b1.y, b1.z, b1.w};

    #pragma unroll
    for (int i = 0; i < 4; i++) {
        int row = row0 + (tr << 2) + i;
        if (row < N) {
            float4 o0 = make_float4(acc[i][0] + bv[0], acc[i][1] + bv[1],
                                    acc[i][2] + bv[2], acc[i][3] + bv[3]);
            float4 o1 = make_float4(acc[i][4] + bv[4], acc[i][5] + bv[5],
                                    acc[i][6] + bv[6], acc[i][7] + bv[7]);
            float4* op = reinterpret_cast<float4*>(out + (size_t)row * D + c0);
            op[0] = o0;
            op[1] = o1;
        }
    }
}

// ---------------------------------------------------------------------------
extern "C" void kernel_launch(void* const* d_in, const int* in_sizes, int n_in,
                              void* d_out, int out_size) {
    const float* feat = (const float*)d_in[0];
    const float* W    = (const float*)d_in[1];
    const float* b    = (const float*)d_in[2];
    const int*   src  = (const int*)d_in[3];
    const int*   dst  = (const int*)d_in[4];
    float*       out  = (float*)d_out;

    int N = in_sizes[0] / D;
    int E = in_sizes[3];

    // 1) zero scratch
    int n4 = (N * D) >> 2;
    k_zero<<<2048, 256>>>(n4);

    // 2) column totals
    k_total<<<1024, D>>>(feat, N);

    // 3) scatter-add (warp per edge)
    long long threads = (long long)E * 32;
    int blocks = (int)((threads + 255) / 256);
    k_scatter<<<blocks, 256>>>(feat, src, dst, E);

    // 4) fused subtract + normalize + GEMM + bias
    size_t shbytes = (size_t)(D * WPAD + TILE_M * D) * sizeof(float);
    cudaFuncSetAttribute(k_out, cudaFuncAttributeMaxDynamicSharedMemorySize, (int)shbytes);
    int gblocks = (N + TILE_M - 1) / TILE_M;
    k_out<<<gblocks, 256, shbytes>>>(W, b, out, N);
}

// round 2
// speedup vs baseline: 1.5722x; 1.5722x over previous
#include <cuda_runtime.h>

#define D 128
#define MAX_N 100000
#define MAX_E 1600000
#define WP 136   // padded W^T row stride (floats), 16B-aligned
#define HP 132   // padded H row stride (floats), 16B-aligned

// Scratch (device globals — no allocations allowed)
__device__ float g_h[(size_t)MAX_N * D];     // normalized h rows
__device__ float g_total[D];
__device__ int   g_cnt[MAX_N];               // degrees, then fill cursor
__device__ int   g_off[MAX_N + 1];           // CSR offsets
__device__ int   g_eidx[MAX_E];              // src ids bucketed by dst
__device__ int   g_bsum[1024];               // scan block sums

// ---------------------------------------------------------------------------
__global__ void k_init(int N) {
    int i = blockIdx.x * blockDim.x + threadIdx.x;
    if (i < N) g_cnt[i] = 0;
    if (i < D) g_total[i] = 0.f;
}

// column sums: total[c] = sum_r feat[r][c]
__global__ void k_total(const float* __restrict__ feat, int N) {
    int c = threadIdx.x;
    float s = 0.f;
    for (int r = blockIdx.x; r < N; r += gridDim.x)
        s += feat[(size_t)r * D + c];
    atomicAdd(&g_total[c], s);
}

__global__ void k_degree(const int* __restrict__ dst, int E) {
    int e = blockIdx.x * blockDim.x + threadIdx.x;
    if (e < E) atomicAdd(&g_cnt[dst[e]], 1);
}

// scan1: per-1024-chunk sums
__global__ void k_scan1(int N) {
    __shared__ int ss[256];
    int base = blockIdx.x * 1024;
    int t = threadIdx.x;
    int s = 0;
    #pragma unroll
    for (int j = 0; j < 4; j++) {
        int i = base + t + j * 256;
        if (i < N) s += g_cnt[i];
    }
    ss[t] = s; __syncthreads();
    for (int o = 128; o; o >>= 1) { if (t < o) ss[t] += ss[t + o]; __syncthreads(); }
    if (t == 0) g_bsum[blockIdx.x] = ss[0];
}

// scan2: exclusive scan of block sums (SB <= 1024), plus g_off[N] = E
__global__ void k_scan2(int SB, int E, int N) {
    __shared__ int ss[1024];
    int t = threadIdx.x;
    for (int i = t; i < SB; i += blockDim.x) ss[i] = g_bsum[i];
    __syncthreads();
    if (t == 0) {
        int run = 0;
        for (int i = 0; i < SB; i++) { int v = ss[i]; ss[i] = run; run += v; }
        g_off[N] = E;
    }
    __syncthreads();
    for (int i = t; i < SB; i += blockDim.x) g_bsum[i] = ss[i];
}

// scan3: per-chunk exclusive scan + global base -> g_off, cursor init
__global__ void k_scan3(int N) {
    __shared__ int ss[256];
    int base = blockIdx.x * 1024;
    int t = threadIdx.x;
    int c[4]; int s = 0;
    #pragma unroll
    for (int j = 0; j < 4; j++) {
        int i = base + t * 4 + j;
        c[j] = (i < N) ? g_cnt[i] : 0;
        s += c[j];
    }
    ss[t] = s; __syncthreads();
    for (int o = 1; o < 256; o <<= 1) {
        int v = (t >= o) ? ss[t - o] : 0;
        __syncthreads();
        ss[t] += v;
        __syncthreads();
    }
    int run = g_bsum[blockIdx.x] + (ss[t] - s);
    #pragma unroll
    for (int j = 0; j < 4; j++) {
        int i = base + t * 4 + j;
        if (i < N) { g_off[i] = run; g_cnt[i] = run; }
        run += c[j];
    }
}

__global__ void k_fill(const int* __restrict__ src, const int* __restrict__ dst, int E) {
    int e = blockIdx.x * blockDim.x + threadIdx.x;
    if (e < E) {
        int pos = atomicAdd(&g_cnt[dst[e]], 1);
        g_eidx[pos] = src[e];
    }
}

// ---------------------------------------------------------------------------
// Gather + subtract + L2-normalize, fused. One warp per dst node.
// Writes normalized h straight to g_h (no zero pass, no float atomics).
// ---------------------------------------------------------------------------
__global__ void k_gather(const float* __restrict__ feat, int N) {
    int wid = (blockIdx.x * blockDim.x + threadIdx.x) >> 5;
    if (wid >= N) return;
    int lane = threadIdx.x & 31;
    int beg = g_off[wid], end = g_off[wid + 1];
    const float4* fp = reinterpret_cast<const float4*>(feat);

    float4 a0 = make_float4(0.f, 0.f, 0.f, 0.f);
    float4 a1 = make_float4(0.f, 0.f, 0.f, 0.f);
    int e = beg;
    for (; e + 4 <= end; e += 4) {
        int s0 = g_eidx[e], s1 = g_eidx[e + 1], s2 = g_eidx[e + 2], s3 = g_eidx[e + 3];
        float4 v0 = fp[(size_t)s0 * 32 + lane];
        float4 v1 = fp[(size_t)s1 * 32 + lane];
        float4 v2 = fp[(size_t)s2 * 32 + lane];
        float4 v3 = fp[(size_t)s3 * 32 + lane];
        a0.x += v0.x + v1.x; a0.y += v0.y + v1.y; a0.z += v0.z + v1.z; a0.w += v0.w + v1.w;
        a1.x += v2.x + v3.x; a1.y += v2.y + v3.y; a1.z += v2.z + v3.z; a1.w += v2.w + v3.w;
    }
    for (; e < end; e++) {
        int s0 = g_eidx[e];
        float4 v0 = fp[(size_t)s0 * 32 + lane];
        a0.x += v0.x; a0.y += v0.y; a0.z += v0.z; a0.w += v0.w;
    }
    a0.x += a1.x; a0.y += a1.y; a0.z += a1.z; a0.w += a1.w;

    float4 tv = reinterpret_cast<const float4*>(g_total)[lane];
    float4 h;
    h.x = tv.x - a0.x; h.y = tv.y - a0.y; h.z = tv.z - a0.z; h.w = tv.w - a0.w;
    float ss = h.x * h.x + h.y * h.y + h.z * h.z + h.w * h.w;
    #pragma unroll
    for (int o = 16; o; o >>= 1) ss += __shfl_xor_sync(0xffffffffu, ss, o);
    float inv = 1.f / fmaxf(sqrtf(ss), 1e-12f);
    h.x *= inv; h.y *= inv; h.z *= inv; h.w *= inv;
    reinterpret_cast<float4*>(g_h + (size_t)wid * D)[lane] = h;
}

// ---------------------------------------------------------------------------
// Pure GEMM: out = g_h @ W^T + b. 512 threads, 256x128 tile, 8x8 per thread.
// ---------------------------------------------------------------------------
__global__ __launch_bounds__(512, 1)
void k_out(const float* __restrict__ W, const float* __restrict__ b,
           float* __restrict__ out, int N) {
    extern __shared__ float sh[];
    float* shW = sh;               // [D][WP]: shW[k*WP + c] = W[c][k]
    float* shH = sh + D * WP;      // [256][HP]

    int tid = threadIdx.x;

    // stage W transposed
    for (int idx = tid; idx < D * D; idx += 512) {
        int c = idx >> 7;
        int k = idx & (D - 1);
        shW[k * WP + c] = W[idx];
    }

    int row0 = blockIdx.x * 256;
    // stage H tile (zero-pad OOB rows)
    for (int idx = tid; idx < 256 * 32; idx += 512) {
        int r = idx >> 5, c4 = idx & 31;
        int row = row0 + r;
        float4 v = make_float4(0.f, 0.f, 0.f, 0.f);
        if (row < N) v = reinterpret_cast<const float4*>(g_h + (size_t)row * D)[c4];
        *reinterpret_cast<float4*>(shH + r * HP + c4 * 4) = v;
    }
    __syncthreads();

    int tr = tid >> 4;       // 0..31
    int tc = tid & 15;       // 0..15
    int r0 = tr << 3;
    int c0 = tc << 3;

    float acc[8][8];
    #pragma unroll
    for (int i = 0; i < 8; i++)
        #pragma unroll
        for (int j = 0; j < 8; j++) acc[i][j] = 0.f;

    const float* hbase = shH + r0 * HP;

    for (int k4 = 0; k4 < 32; k4++) {
        int k = k4 << 2;
        float4 w0[4], w1[4];
        #pragma unroll
        for (int kk = 0; kk < 4; kk++) {
            w0[kk] = *reinterpret_cast<const float4*>(shW + (k + kk) * WP + c0);
            w1[kk] = *reinterpret_cast<const float4*>(shW + (k + kk) * WP + c0 + 4);
        }
        #pragma unroll
        for (int i = 0; i < 8; i++) {
            float4 hv = *reinterpret_cast<const float4*>(hbase + i * HP + k);
            float hvv[4] = {hv.x, hv.y, hv.z, hv.w};
            #pragma unroll
            for (int kk = 0; kk < 4; kk++) {
                float hk = hvv[kk];
                acc[i][0] = fmaf(hk, w0[kk].x, acc[i][0]);
                acc[i][1] = fmaf(hk, w0[kk].y, acc[i][1]);
                acc[i][2] = fmaf(hk, w0[kk].z, acc[i][2]);
                acc[i][3] = fmaf(hk, w0[kk].w, acc[i][3]);
                acc[i][4] = fmaf(hk, w1[kk].x, acc[i][4]);
                acc[i][5] = fmaf(hk, w1[kk].y, acc[i][5]);
                acc[i][6] = fmaf(hk, w1[kk].z, acc[i][6]);
                acc[i][7] = fmaf(hk, w1[kk].w, acc[i][7]);
            }
        }
    }

    float4 b0 = *reinterpret_cast<const float4*>(b + c0);
    float4 b1 = *reinterpret_cast<const float4*>(b + c0 + 4);
    float bv[8] = {b0.x, b0.y, b0.z, b0.w, b1.x, b1.y, b1.z, b1.w};

    #pragma unroll
    for (int i = 0; i < 8; i++) {
        int row = row0 + r0 + i;
        if (row < N) {
            float4 o0 = make_float4(acc[i][0] + bv[0], acc[i][1] + bv[1],
                                    acc[i][2] + bv[2], acc[i][3] + bv[3]);
            float4 o1 = make_float4(acc[i][4] + bv[4], acc[i][5] + bv[5],
                                    acc[i][6] + bv[6], acc[i][7] + bv[7]);
            float4* op = reinterpret_cast<float4*>(out + (size_t)row * D + c0);
            op[0] = o0;
            op[1] = o1;
        }
    }
}

// ---------------------------------------------------------------------------
extern "C" void kernel_launch(void* const* d_in, const int* in_sizes, int n_in,
                              void* d_out, int out_size) {
    const float* feat = (const float*)d_in[0];
    const float* W    = (const float*)d_in[1];
    const float* b    = (const float*)d_in[2];
    const int*   src  = (const int*)d_in[3];
    const int*   dst  = (const int*)d_in[4];
    float*       out  = (float*)d_out;

    int N = in_sizes[0] / D;
    int E = in_sizes[3];
    int SB = (N + 1023) / 1024;

    k_init<<<(N + 255) / 256, 256>>>(N);
    k_total<<<1024, D>>>(feat, N);
    k_degree<<<(E + 255) / 256, 256>>>(dst, E);
    k_scan1<<<SB, 256>>>(N);
    k_scan2<<<1, 128>>>(SB, E, N);
    k_scan3<<<SB, 256>>>(N);
    k_fill<<<(E + 255) / 256, 256>>>(src, dst, E);
    k_gather<<<(N + 7) / 8, 256>>>(feat, N);

    size_t shbytes = (size_t)(D * WP + 256 * HP) * sizeof(float);
    cudaFuncSetAttribute(k_out, cudaFuncAttributeMaxDynamicSharedMemorySize, (int)shbytes);
    k_out<<<(N + 255) / 256, 512, shbytes>>>(W, b, out, N);
}